// round 6
// baseline (speedup 1.0000x reference)
#include <cuda_runtime.h>
#include <math.h>

#define BB 8
#define AA 64
#define DE 128
#define MM 512
#define DH 64
#define ZD 128

__device__ float g_dH2[BB * MM];
__device__ float g_logv[BB * MM * DH];

__device__ __forceinline__ float warp_sum(float v) {
#pragma unroll
    for (int o = 16; o > 0; o >>= 1) v += __shfl_xor_sync(0xffffffffu, v, o);
    return v;
}

// ---------------------------------------------------------------------------
// Prologue: per (b,m) Poincare dH2 + log-map vector. One warp per (b,m).
// ---------------------------------------------------------------------------
__global__ void __launch_bounds__(256) prologue_kernel(
    const float* __restrict__ currH,   // [B, DH]
    const float* __restrict__ demoH)   // [B*M, DH]
{
    int gw = blockIdx.x * 8 + (threadIdx.x >> 5);
    int l = threadIdx.x & 31;
    if (gw >= BB * MM) return;
    int b = gw >> 9;

    float x0 = currH[b * DH + 2 * l], x1 = currH[b * DH + 2 * l + 1];
    float y0 = demoH[(size_t)gw * DH + 2 * l], y1 = demoH[(size_t)gw * DH + 2 * l + 1];

    const float thr = 1.0f - 1e-5f;
    float x2 = warp_sum(x0 * x0 + x1 * x1);
    float nx = fmaxf(sqrtf(x2), 1e-15f);
    if (nx > thr) { float s = thr / nx; x0 *= s; x1 *= s; x2 *= s * s; }
    float y2 = warp_sum(y0 * y0 + y1 * y1);
    float ny = fmaxf(sqrtf(y2), 1e-15f);
    if (ny > thr) { float s = thr / ny; y0 *= s; y1 *= s; y2 *= s * s; }

    float xy = warp_sum(x0 * y0 + x1 * y1);

    float Ac = 1.0f - 2.0f * xy + y2;
    float Bc = 1.0f - x2;
    float den = fmaxf(1.0f - 2.0f * xy + x2 * y2, 1e-15f);
    float inv = 1.0f / den;
    float u0 = (Bc * y0 - Ac * x0) * inv;
    float u1 = (Bc * y1 - Ac * x1) * inv;

    float un2 = warp_sum(u0 * u0 + u1 * u1);
    float un = fmaxf(sqrtf(un2), 1e-15f);
    float arg = fminf(un, 1.0f - 1e-7f);
    float at = atanhf(arg);

    if (l == 0) g_dH2[gw] = 4.0f * at * at;

    float sc = fmaxf(1.0f - x2, 1e-15f) * at / un;
    g_logv[(size_t)gw * DH + 2 * l]     = sc * u0;
    g_logv[(size_t)gw * DH + 2 * l + 1] = sc * u1;
}

// ---------------------------------------------------------------------------
// Main: one CTA per (b,a). 256 threads, 8 warps; each warp split in 4 groups
// of 8 lanes; group handles one m per iteration (m = 32i + 4w + g).
// Lane j of a group owns cols {32k+4j..+3} (4 float4 loads, contiguous per
// group) and v-dims {16t+2j,+1}. 3-stage shuffle reduce, 1 exp per m.
// Group-local online softmax; 32 partial states merged in smem.
// ---------------------------------------------------------------------------
__global__ void __launch_bounds__(256, 3) main_kernel(
    const float* __restrict__ curr_rho,  // [B, A, DE]
    const float* __restrict__ currH,     // [B, DH]
    const float* __restrict__ demo_rho,  // [B, M, A, DE]
    const float* __restrict__ We,        // [64, DE]
    const float* __restrict__ Wh,        // [64, DH]
    const float* __restrict__ gamma,     // [ZD]
    const float* __restrict__ beta,      // [ZD]
    float* __restrict__ out)             // [B, A, ZD]
{
    const int bx = blockIdx.x;           // b*AA + a
    const int b = bx >> 6, a = bx & 63;
    const int tid = threadIdx.x;
    const int w = tid >> 5, l = tid & 31;
    const int g = l >> 3, j = l & 7;

    __shared__ float s_h2[MM];
    __shared__ float s_mx[32], s_sm[32];
    __shared__ float s_acce[32][DE];
    __shared__ float s_accv[32][DH];
    __shared__ float s_eout[DE];
    __shared__ float s_v[DH];
    __shared__ float s_h[DH];
    __shared__ float s_red[8];

    // preload dH2 for this b
    {
        const float2* p = reinterpret_cast<const float2*>(g_dH2 + b * MM);
        reinterpret_cast<float2*>(s_h2)[tid] = p[tid];
    }
    __syncthreads();

    // current vector: lane j needs cols 32k+4j (k=0..3)
    float4 cur4[4];
    {
        const float4* cp = reinterpret_cast<const float4*>(curr_rho) + (size_t)bx * (DE / 4);
#pragma unroll
        for (int k = 0; k < 4; k++) cur4[k] = cp[8 * k + j];
    }

    float mx = -3.0e38f, sm = 0.f;
    float4 acce[4];
    float2 accv[4];
#pragma unroll
    for (int k = 0; k < 4; k++) acce[k] = make_float4(0.f, 0.f, 0.f, 0.f);
#pragma unroll
    for (int t = 0; t < 4; t++) accv[t] = make_float2(0.f, 0.f);

    const int m0 = 4 * w + g;            // m = 32*i + m0
    const float* dbase = demo_rho + ((size_t)(b * MM + m0) * AA + a) * DE + 4 * j;
    const float* lbase = g_logv + (size_t)(b * MM + m0) * DH + 2 * j;
    const size_t dstep = (size_t)32 * AA * DE;   // m += 32
    const size_t lstep = (size_t)32 * DH;

    for (int i = 0; i < 16; i++) {
        const float* dp = dbase + (size_t)i * dstep;
        const float* lp = lbase + (size_t)i * lstep;
        float4 dv[4]; float2 lv[4];
#pragma unroll
        for (int k = 0; k < 4; k++) dv[k] = *reinterpret_cast<const float4*>(dp + 32 * k);
#pragma unroll
        for (int t = 0; t < 4; t++) lv[t] = *reinterpret_cast<const float2*>(lp + 16 * t);
        float h2m = s_h2[32 * i + m0];

        float part = 0.f;
#pragma unroll
        for (int k = 0; k < 4; k++) {
            float d0 = cur4[k].x - dv[k].x, d1 = cur4[k].y - dv[k].y;
            float d2 = cur4[k].z - dv[k].z, d3 = cur4[k].w - dv[k].w;
            part += d0 * d0 + d1 * d1 + d2 * d2 + d3 * d3;
        }
        // 3-stage butterfly within the 8-lane group
        part += __shfl_xor_sync(0xffffffffu, part, 1);
        part += __shfl_xor_sync(0xffffffffu, part, 2);
        part += __shfl_xor_sync(0xffffffffu, part, 4);
        float s = -(part + h2m);

        float nm = fmaxf(mx, s);
        if (__any_sync(0xffffffffu, nm > mx)) {      // warp-uniform branch
            float c = __expf(mx - nm);               // ==1 for non-updating groups
            mx = nm;
            sm *= c;
#pragma unroll
            for (int k = 0; k < 4; k++) {
                acce[k].x *= c; acce[k].y *= c; acce[k].z *= c; acce[k].w *= c;
            }
#pragma unroll
            for (int t = 0; t < 4; t++) { accv[t].x *= c; accv[t].y *= c; }
        }
        float p = __expf(s - mx);
        sm += p;
#pragma unroll
        for (int k = 0; k < 4; k++) {
            acce[k].x += p * dv[k].x; acce[k].y += p * dv[k].y;
            acce[k].z += p * dv[k].z; acce[k].w += p * dv[k].w;
        }
#pragma unroll
        for (int t = 0; t < 4; t++) { accv[t].x += p * lv[t].x; accv[t].y += p * lv[t].y; }
    }

    // store 32 group states
    const int st = 4 * w + g;
    if (j == 0) { s_mx[st] = mx; s_sm[st] = sm; }
#pragma unroll
    for (int k = 0; k < 4; k++)
        *reinterpret_cast<float4*>(&s_acce[st][32 * k + 4 * j]) = acce[k];
#pragma unroll
    for (int t = 0; t < 4; t++)
        *reinterpret_cast<float2*>(&s_accv[st][16 * t + 2 * j]) = accv[t];
    __syncthreads();

    // merge 32 states
    float gmax = -3.0e38f;
#pragma unroll
    for (int q = 0; q < 32; q++) gmax = fmaxf(gmax, s_mx[q]);
    float S = 0.f;
#pragma unroll
    for (int q = 0; q < 32; q++) S += __expf(s_mx[q] - gmax) * s_sm[q];
    float invS = 1.0f / S;

    if (tid < DE) {
        float e = 0.f;
#pragma unroll
        for (int q = 0; q < 32; q++) e += __expf(s_mx[q] - gmax) * s_acce[q][tid];
        s_eout[tid] = e * invS;
    } else if (tid < DE + DH) {
        int d = tid - DE;
        float v = 0.f;
#pragma unroll
        for (int q = 0; q < 32; q++) v += __expf(s_mx[q] - gmax) * s_accv[q][d];
        s_v[d] = v * invS;
    }
    __syncthreads();

    // exp-map on warp 0 (lane l owns dims 2l, 2l+1)
    if (w == 0) {
        float x0 = currH[b * DH + 2 * l], x1 = currH[b * DH + 2 * l + 1];
        const float thr = 1.0f - 1e-5f;
        float x2 = warp_sum(x0 * x0 + x1 * x1);
        float nx = fmaxf(sqrtf(x2), 1e-15f);
        if (nx > thr) { float s0 = thr / nx; x0 *= s0; x1 *= s0; x2 *= s0 * s0; }
        float lam = 2.0f / fmaxf(1.0f - x2, 1e-15f);

        float v0 = s_v[2 * l], v1 = s_v[2 * l + 1];
        float vn2 = warp_sum(v0 * v0 + v1 * v1);
        float vn = fmaxf(sqrtf(vn2), 1e-15f);
        float fac = tanhf(lam * vn * 0.5f);
        float iv = fac / vn;
        float y0 = v0 * iv, y1 = v1 * iv;

        float yn2 = warp_sum(y0 * y0 + y1 * y1);
        float yn = fmaxf(sqrtf(yn2), 1e-15f);
        if (yn > thr) { float s0 = thr / yn; y0 *= s0; y1 *= s0; yn2 *= s0 * s0; }

        float xy = warp_sum(x0 * y0 + x1 * y1);
        float den = fmaxf(1.0f + 2.0f * xy + x2 * yn2, 1e-15f);
        float ca = (1.0f + 2.0f * xy + yn2) / den;
        float cb2 = (1.0f - x2) / den;
        float o0 = ca * x0 + cb2 * y0, o1 = ca * x1 + cb2 * y1;

        float on2 = warp_sum(o0 * o0 + o1 * o1);
        float on = fmaxf(sqrtf(on2), 1e-15f);
        if (on > thr) { float s0 = thr / on; o0 *= s0; o1 *= s0; }
        s_h[2 * l] = o0; s_h[2 * l + 1] = o1;
    }
    __syncthreads();

    // GEMVs + LayerNorm
    float zj = 0.f;
    if (tid < ZD) {
        if (tid < 64) {
            const float* wr = We + tid * DE;
#pragma unroll 8
            for (int d = 0; d < DE; d++) zj += wr[d] * s_eout[d];
        } else {
            const float* wr = Wh + (tid - 64) * DH;
#pragma unroll 8
            for (int d = 0; d < DH; d++) zj += wr[d] * s_h[d];
        }
        float p1 = warp_sum(zj);
        float p2 = warp_sum(zj * zj);
        if (l == 0) { s_red[w] = p1; s_red[4 + w] = p2; }
    }
    __syncthreads();
    if (tid < ZD) {
        float sum = s_red[0] + s_red[1] + s_red[2] + s_red[3];
        float sq  = s_red[4] + s_red[5] + s_red[6] + s_red[7];
        float mean = sum * (1.0f / ZD);
        float var = sq * (1.0f / ZD) - mean * mean;
        float r = rsqrtf(var + 1e-5f);
        out[(size_t)bx * ZD + tid] = (zj - mean) * r * gamma[tid] + beta[tid];
    }
}

extern "C" void kernel_launch(void* const* d_in, const int* in_sizes, int n_in,
                              void* d_out, int out_size) {
    const float* curr_rho = (const float*)d_in[0];
    const float* currH    = (const float*)d_in[1];
    const float* demo_rho = (const float*)d_in[2];
    const float* demoH    = (const float*)d_in[3];
    const float* We       = (const float*)d_in[4];
    const float* Wh       = (const float*)d_in[5];
    const float* gamma    = (const float*)d_in[6];
    const float* beta     = (const float*)d_in[7];
    float* out = (float*)d_out;

    prologue_kernel<<<512, 256>>>(currH, demoH);
    main_kernel<<<BB * AA, 256>>>(curr_rho, currH, demo_rho, We, Wh, gamma, beta, out);
}

// round 10
// speedup vs baseline: 1.3314x; 1.3314x over previous
#include <cuda_runtime.h>
#include <math.h>
#include <stdint.h>

#define BB 8
#define AA 64
#define DE 128
#define MM 512
#define DH 64
#define ZD 128

#define SMQ 8          // m per stage
#define NBUF 4         // smem buffers
#define NST 64         // stages = MM/SMQ

__device__ float g_dH2[BB * MM];
__device__ float g_logv[BB * MM * DH];

__device__ __forceinline__ float warp_sum(float v) {
#pragma unroll
    for (int o = 16; o > 0; o >>= 1) v += __shfl_xor_sync(0xffffffffu, v, o);
    return v;
}

__device__ __forceinline__ void cp16(unsigned int dst, const void* src) {
    asm volatile("cp.async.cg.shared.global [%0], [%1], 16;\n" :: "r"(dst), "l"(src));
}
__device__ __forceinline__ void cp_commit() {
    asm volatile("cp.async.commit_group;\n" ::: "memory");
}
__device__ __forceinline__ void cp_wait2() {
    asm volatile("cp.async.wait_group 2;\n" ::: "memory");
}

// ---------------------------------------------------------------------------
// Prologue: per (b,m) Poincare dH2 + log-map vector. One warp per (b,m).
// ---------------------------------------------------------------------------
__global__ void __launch_bounds__(256) prologue_kernel(
    const float* __restrict__ currH,   // [B, DH]
    const float* __restrict__ demoH)   // [B*M, DH]
{
    int gw = blockIdx.x * 8 + (threadIdx.x >> 5);
    int l = threadIdx.x & 31;
    if (gw >= BB * MM) return;
    int b = gw >> 9;

    float x0 = currH[b * DH + 2 * l], x1 = currH[b * DH + 2 * l + 1];
    float y0 = demoH[(size_t)gw * DH + 2 * l], y1 = demoH[(size_t)gw * DH + 2 * l + 1];

    const float thr = 1.0f - 1e-5f;
    float x2 = warp_sum(x0 * x0 + x1 * x1);
    float nx = fmaxf(sqrtf(x2), 1e-15f);
    if (nx > thr) { float s = thr / nx; x0 *= s; x1 *= s; x2 *= s * s; }
    float y2 = warp_sum(y0 * y0 + y1 * y1);
    float ny = fmaxf(sqrtf(y2), 1e-15f);
    if (ny > thr) { float s = thr / ny; y0 *= s; y1 *= s; y2 *= s * s; }

    float xy = warp_sum(x0 * y0 + x1 * y1);

    float Ac = 1.0f - 2.0f * xy + y2;
    float Bc = 1.0f - x2;
    float den = fmaxf(1.0f - 2.0f * xy + x2 * y2, 1e-15f);
    float inv = 1.0f / den;
    float u0 = (Bc * y0 - Ac * x0) * inv;
    float u1 = (Bc * y1 - Ac * x1) * inv;

    float un2 = warp_sum(u0 * u0 + u1 * u1);
    float un = fmaxf(sqrtf(un2), 1e-15f);
    float arg = fminf(un, 1.0f - 1e-7f);
    float at = atanhf(arg);

    if (l == 0) g_dH2[gw] = 4.0f * at * at;

    float sc = fmaxf(1.0f - x2, 1e-15f) * at / un;
    g_logv[(size_t)gw * DH + 2 * l]     = sc * u0;
    g_logv[(size_t)gw * DH + 2 * l + 1] = sc * u1;
}

// ---------------------------------------------------------------------------
// Main: one CTA per (b,a). 256 threads / 8 warps. cp.async pipeline:
// 64 stages x 8 m; 4 buffers; issue-ahead 3. Warp w consumes m = 8*stage + w
// from smem (lane owns 4 cols), online softmax, in-register e/v accumulators.
// ---------------------------------------------------------------------------
__global__ void __launch_bounds__(256, 5) main_kernel(
    const float* __restrict__ curr_rho,  // [B, A, DE]
    const float* __restrict__ currH,     // [B, DH]
    const float* __restrict__ demo_rho,  // [B, M, A, DE]
    const float* __restrict__ We,        // [64, DE]
    const float* __restrict__ Wh,        // [64, DH]
    const float* __restrict__ gamma,     // [ZD]
    const float* __restrict__ beta,      // [ZD]
    float* __restrict__ out)             // [B, A, ZD]
{
    const int bx = blockIdx.x;           // b*AA + a
    const int b = bx >> 6, a = bx & 63;
    const int tid = threadIdx.x;
    const int w = tid >> 5, l = tid & 31;

    __shared__ float sd[NBUF][SMQ][DE];   // 16 KB demo stage
    __shared__ float sl[NBUF][SMQ][DH];   //  8 KB logv stage
    __shared__ float s_h2[MM];            //  2 KB
    __shared__ float s_mx[8], s_sm[8], s_red[8];
    __shared__ float s_acce[8][DE];
    __shared__ float s_accv[8][DH];
    __shared__ float s_eout[DE];
    __shared__ float s_v[DH];
    __shared__ float s_h[DH];

    // preload dH2 for this b (512 floats, L2-resident)
    {
        const float2* p = reinterpret_cast<const float2*>(g_dH2 + b * MM);
        reinterpret_cast<float2*>(s_h2)[tid] = p[tid];
    }

    // per-thread cp.async source/dest precompute
    const int d_ml = tid >> 5, d_c = tid & 31;          // demo: 8 m x 32 chunks
    const float* d_src0 = demo_rho + (((size_t)(b * MM + d_ml)) * AA + a) * DE + 4 * d_c;
    unsigned int d_dst0 = (unsigned int)__cvta_generic_to_shared(&sd[0][d_ml][4 * d_c]);
    const int l_ml = (tid & 127) >> 4, l_c = tid & 15;  // logv: 8 m x 16 chunks (tid<128)
    const float* l_src0 = g_logv + ((size_t)(b * MM + l_ml)) * DH + 4 * l_c;
    unsigned int l_dst0 = (unsigned int)__cvta_generic_to_shared(&sl[0][l_ml][4 * l_c]);
    const size_t d_step = (size_t)SMQ * AA * DE;        // per-stage gmem step (floats)
    const size_t l_step = (size_t)SMQ * DH;
    const unsigned int sd_bytes = SMQ * DE * 4, sl_bytes = SMQ * DH * 4;

    // issue stages 0..2
#pragma unroll
    for (int q = 0; q < 3; q++) {
        cp16(d_dst0 + (q & (NBUF - 1)) * sd_bytes, d_src0 + (size_t)q * d_step);
        if (tid < 128) cp16(l_dst0 + (q & (NBUF - 1)) * sl_bytes, l_src0 + (size_t)q * l_step);
        cp_commit();
    }

    // current vector: lane owns cols 4l..4l+3
    const float4 cur = reinterpret_cast<const float4*>(curr_rho)[(size_t)bx * (DE / 4) + l];

    float mx = -3.0e38f, sm = 0.f;
    float4 ae = make_float4(0.f, 0.f, 0.f, 0.f);
    float av0 = 0.f, av1 = 0.f;

    for (int k = 0; k < NST; k++) {
        cp_wait2();
        __syncthreads();
        const int buf = k & (NBUF - 1);

        float4 dv = *reinterpret_cast<const float4*>(&sd[buf][w][4 * l]);
        float2 lv = *reinterpret_cast<const float2*>(&sl[buf][w][2 * l]);
        float h2m = s_h2[SMQ * k + w];

        float d0 = cur.x - dv.x, d1 = cur.y - dv.y;
        float d2 = cur.z - dv.z, d3 = cur.w - dv.w;
        float part = (d0 * d0 + d1 * d1) + (d2 * d2 + d3 * d3);
        part += __shfl_xor_sync(0xffffffffu, part, 1);
        part += __shfl_xor_sync(0xffffffffu, part, 2);
        part += __shfl_xor_sync(0xffffffffu, part, 4);
        part += __shfl_xor_sync(0xffffffffu, part, 8);
        part += __shfl_xor_sync(0xffffffffu, part, 16);
        float s = -(part + h2m);            // warp-uniform

        if (s > mx) {                       // warp-uniform branch
            float c = __expf(mx - s);
            mx = s;
            sm *= c;
            ae.x *= c; ae.y *= c; ae.z *= c; ae.w *= c;
            av0 *= c; av1 *= c;
        }
        float p = __expf(s - mx);
        sm += p;
        ae.x += p * dv.x; ae.y += p * dv.y;
        ae.z += p * dv.z; ae.w += p * dv.w;
        av0 += p * lv.x;  av1 += p * lv.y;

        // issue stage k+3 (buffer (k+3)&3: its old occupant k-1 was consumed
        // before the sync above)
        if (k + 3 < NST) {
            cp16(d_dst0 + ((k + 3) & (NBUF - 1)) * sd_bytes, d_src0 + (size_t)(k + 3) * d_step);
            if (tid < 128) cp16(l_dst0 + ((k + 3) & (NBUF - 1)) * sl_bytes, l_src0 + (size_t)(k + 3) * l_step);
        }
        cp_commit();   // commit every iter (possibly empty) to keep group count uniform
    }

    // store 8 warp states
    if (l == 0) { s_mx[w] = mx; s_sm[w] = sm; }
    *reinterpret_cast<float4*>(&s_acce[w][4 * l]) = ae;
    s_accv[w][2 * l] = av0; s_accv[w][2 * l + 1] = av1;
    __syncthreads();

    // merge 8 states
    float gmax = -3.0e38f;
#pragma unroll
    for (int q = 0; q < 8; q++) gmax = fmaxf(gmax, s_mx[q]);
    float S = 0.f;
#pragma unroll
    for (int q = 0; q < 8; q++) S += __expf(s_mx[q] - gmax) * s_sm[q];
    float invS = 1.0f / S;

    if (tid < DE) {
        float e = 0.f;
#pragma unroll
        for (int q = 0; q < 8; q++) e += __expf(s_mx[q] - gmax) * s_acce[q][tid];
        s_eout[tid] = e * invS;
    } else if (tid < DE + DH) {
        int d = tid - DE;
        float v = 0.f;
#pragma unroll
        for (int q = 0; q < 8; q++) v += __expf(s_mx[q] - gmax) * s_accv[q][d];
        s_v[d] = v * invS;
    }
    __syncthreads();

    // exp-map on warp 0 (lane l owns dims 2l, 2l+1)
    if (w == 0) {
        float x0 = currH[b * DH + 2 * l], x1 = currH[b * DH + 2 * l + 1];
        const float thr = 1.0f - 1e-5f;
        float x2 = warp_sum(x0 * x0 + x1 * x1);
        float nx = fmaxf(sqrtf(x2), 1e-15f);
        if (nx > thr) { float s0 = thr / nx; x0 *= s0; x1 *= s0; x2 *= s0 * s0; }
        float lam = 2.0f / fmaxf(1.0f - x2, 1e-15f);

        float v0 = s_v[2 * l], v1 = s_v[2 * l + 1];
        float vn2 = warp_sum(v0 * v0 + v1 * v1);
        float vn = fmaxf(sqrtf(vn2), 1e-15f);
        float fac = tanhf(lam * vn * 0.5f);
        float iv = fac / vn;
        float y0 = v0 * iv, y1 = v1 * iv;

        float yn2 = warp_sum(y0 * y0 + y1 * y1);
        float yn = fmaxf(sqrtf(yn2), 1e-15f);
        if (yn > thr) { float s0 = thr / yn; y0 *= s0; y1 *= s0; yn2 *= s0 * s0; }

        float xy = warp_sum(x0 * y0 + x1 * y1);
        float den = fmaxf(1.0f + 2.0f * xy + x2 * yn2, 1e-15f);
        float ca = (1.0f + 2.0f * xy + yn2) / den;
        float cb2 = (1.0f - x2) / den;
        float o0 = ca * x0 + cb2 * y0, o1 = ca * x1 + cb2 * y1;

        float on2 = warp_sum(o0 * o0 + o1 * o1);
        float on = fmaxf(sqrtf(on2), 1e-15f);
        if (on > thr) { float s0 = thr / on; o0 *= s0; o1 *= s0; }
        s_h[2 * l] = o0; s_h[2 * l + 1] = o1;
    }
    __syncthreads();

    // GEMVs + LayerNorm (threads 0..127 produce z[j])
    float zj = 0.f;
    if (tid < ZD) {
        if (tid < 64) {
            const float* wr = We + tid * DE;
#pragma unroll 8
            for (int d = 0; d < DE; d++) zj += wr[d] * s_eout[d];
        } else {
            const float* wr = Wh + (tid - 64) * DH;
#pragma unroll 8
            for (int d = 0; d < DH; d++) zj += wr[d] * s_h[d];
        }
        float p1 = warp_sum(zj);
        float p2 = warp_sum(zj * zj);
        if (l == 0) { s_red[w] = p1; s_red[4 + w] = p2; }
    }
    __syncthreads();
    if (tid < ZD) {
        float sum = s_red[0] + s_red[1] + s_red[2] + s_red[3];
        float sq  = s_red[4] + s_red[5] + s_red[6] + s_red[7];
        float mean = sum * (1.0f / ZD);
        float var = sq * (1.0f / ZD) - mean * mean;
        float r = rsqrtf(var + 1e-5f);
        out[(size_t)bx * ZD + tid] = (zj - mean) * r * gamma[tid] + beta[tid];
    }
}

extern "C" void kernel_launch(void* const* d_in, const int* in_sizes, int n_in,
                              void* d_out, int out_size) {
    const float* curr_rho = (const float*)d_in[0];
    const float* currH    = (const float*)d_in[1];
    const float* demo_rho = (const float*)d_in[2];
    const float* demoH    = (const float*)d_in[3];
    const float* We       = (const float*)d_in[4];
    const float* Wh       = (const float*)d_in[5];
    const float* gamma    = (const float*)d_in[6];
    const float* beta     = (const float*)d_in[7];
    float* out = (float*)d_out;

    prologue_kernel<<<512, 256>>>(currH, demoH);
    main_kernel<<<BB * AA, 256>>>(curr_rho, currH, demo_rho, We, Wh, gamma, beta, out);
}